// round 8
// baseline (speedup 1.0000x reference)
#include <cuda_runtime.h>
#include <math.h>
#include <stdint.h>

#define TWO_PI 6.28318530717958647692f

// Scratch
__device__ float g_pq[128 * 3 * 2 * 64 * 128];   // [h][v][s(0=cos,1=sin)][c][o]
__device__ float g_stats[512];                   // [part][o][sum,sumsq]
__device__ float g_bnp[512];                     // [part][o][scale,shift]

__device__ __forceinline__ uint32_t f2tf(float x) {
    uint32_t u;
    asm("cvt.rna.tf32.f32 %0, %1;" : "=r"(u) : "f"(x));
    return u;
}
__device__ __forceinline__ void mma_tf32(float* d, const uint32_t* a,
                                         const uint32_t* b) {
    asm volatile(
        "mma.sync.aligned.m16n8k8.row.col.f32.tf32.tf32.f32 "
        "{%0,%1,%2,%3}, {%4,%5,%6,%7}, {%8,%9}, {%0,%1,%2,%3};"
        : "+f"(d[0]), "+f"(d[1]), "+f"(d[2]), "+f"(d[3])
        : "r"(a[0]), "r"(a[1]), "r"(a[2]), "r"(a[3]), "r"(b[0]), "r"(b[1]));
}

// ---------------------------------------------------------------------------
__global__ void zero_stats_kernel() {
    if (threadIdx.x < 512) g_stats[threadIdx.x] = 0.f;
}

// P_v[h][c][o] = sum_u cos(2*pi*h*u/128) * f[u][v][c][o]   (s=0)
// Q_v[h][c][o] = sum_u sin(...) * f[u][v][c][o]            (s=1)
__global__ void precompute_pq_kernel(const float* __restrict__ filters) {
    __shared__ float ct[128], st[128];
    int h = blockIdx.x, t = threadIdx.x;
    if (t < 128) {
        float s_, c_;
        sincosf(TWO_PI * (float)t * (1.f / 128.f), &s_, &c_);
        ct[t] = c_; st[t] = s_;
    }
    __syncthreads();
    for (int e = t; e < 3 * 2 * 64 * 128; e += blockDim.x) {
        int v = e >> 14, s = (e >> 13) & 1, co = e & 8191;
        float acc = 0.f;
        #pragma unroll
        for (int u = 0; u < 3; u++) {
            int a = (h * u) & 127;
            float tr = s ? st[a] : ct[a];
            acc = fmaf(tr, filters[(u * 3 + v) * 8192 + co], acc);
        }
        g_pq[((h * 3 + v) * 2 + s) * 8192 + co] = acc;
    }
}

// ---------------------------------------------------------------------------
// Conv kernel: grid (128 h, 4 och), 256 threads, tf32 mma.sync GEMM.
// Per 8-pixel group:
//  stage X: S=r+i rows 0..7, D=i-r rows 8..15, tf32 bits, Xt[(pix*64+c)*24 + r]
//  build M from register P/Q slices -> tf32 bits, Ms[(pix*64+c)*40 + o]
//  GEMM: warp = pixel, D[16x32] = Xrows[16x64] x M[64x32] via m16n8k8
#define XT_OFF 81920
#define CT_OFF 131072
#define ST_OFF 131584
#define RED_OFF 132096
#define SMEM_BYTES 132608

__global__ __launch_bounds__(256, 1) void conv_mma_kernel(
    const float* __restrict__ xr, const float* __restrict__ xi,
    float* __restrict__ out)
{
    extern __shared__ char smem[];
    uint32_t* Ms = (uint32_t*)smem;                   // [8*64][40]
    uint32_t* Xt = (uint32_t*)(smem + XT_OFF);        // [8*64][24]
    float* ct = (float*)(smem + CT_OFF);
    float* st = (float*)(smem + ST_OFF);
    float* red = (float*)(smem + RED_OFF);            // [2][32][2]

    const int h = blockIdx.x;
    const int och = blockIdx.y;
    const int t = threadIdx.x;
    const int lane = t & 31;
    const int wid = t >> 5;
    const int tg = lane & 3;       // threadID in group (k / col-pair)
    const int gid = lane >> 2;     // group id (row)

    if (t < 128) {
        float s_, c_;
        sincosf(TWO_PI * (float)t * (1.f / 128.f), &s_, &c_);
        ct[t] = c_; st[t] = s_;
        red[t] = 0.f;
    }

    // register-resident P/Q slice (verified R1 scheme): c = 2cp,2cp+1; 4 o's
    const int cp = t >> 3;
    const int oq = t & 7;
    const int obase = och * 32 + oq * 4;
    float4 P0[2], P1[2], Q1[2], P2[2], Q2[2];
    #pragma unroll
    for (int j = 0; j < 2; j++) {
        int c = 2 * cp + j;
        const float* b = g_pq + (size_t)h * 6 * 8192 + c * 128 + obase;
        P0[j] = *(const float4*)(b + 0 * 8192);
        P1[j] = *(const float4*)(b + 2 * 8192);
        Q1[j] = *(const float4*)(b + 3 * 8192);
        P2[j] = *(const float4*)(b + 4 * 8192);
        Q2[j] = *(const float4*)(b + 5 * 8192);
    }

    // BN stat accumulators: [part(2)][nt(4)][col-pair(2)]
    float ssum[16], ssq[16];
    #pragma unroll
    for (int i = 0; i < 16; i++) { ssum[i] = 0.f; ssq[i] = 0.f; }

    for (int w0 = 0; w0 < 128; w0 += 8) {
        __syncthreads();   // protect Ms/Xt vs previous group's GEMM reads

        // ---- stage X (tf32) ----
        #pragma unroll
        for (int k = 0; k < 4; k++) {
            int id = k * 256 + t;
            int pix = id >> 7;
            int n = id & 7;
            int c4 = ((id >> 3) & 15) << 2;
            size_t g = ((((size_t)n * 128 + h) * 128) + (w0 + pix)) * 64 + c4;
            float4 r = *(const float4*)(xr + g);
            float4 im = *(const float4*)(xi + g);
            uint32_t* xp = Xt + (pix * 64 + c4) * 24 + n;
            xp[0]       = f2tf(r.x + im.x);
            xp[24]      = f2tf(r.y + im.y);
            xp[48]      = f2tf(r.z + im.z);
            xp[72]      = f2tf(r.w + im.w);
            xp[8]       = f2tf(im.x - r.x);
            xp[32]      = f2tf(im.y - r.y);
            xp[56]      = f2tf(im.z - r.z);
            xp[80]      = f2tf(im.w - r.w);
        }

        // ---- build M (tf32) ----
        #pragma unroll
        for (int pix = 0; pix < 8; pix++) {
            int w = w0 + pix;
            float cw1 = ct[w], sw1 = st[w];
            int w2 = (w + w) & 127;
            float cw2 = ct[w2], sw2 = st[w2];
            #pragma unroll
            for (int j = 0; j < 2; j++) {
                int c = 2 * cp + j;
                float4 m;
                m.x = fmaf(cw1, P1[j].x, P0[j].x);
                m.y = fmaf(cw1, P1[j].y, P0[j].y);
                m.z = fmaf(cw1, P1[j].z, P0[j].z);
                m.w = fmaf(cw1, P1[j].w, P0[j].w);
                m.x = fmaf(-sw1, Q1[j].x, m.x);
                m.y = fmaf(-sw1, Q1[j].y, m.y);
                m.z = fmaf(-sw1, Q1[j].z, m.z);
                m.w = fmaf(-sw1, Q1[j].w, m.w);
                m.x = fmaf(cw2, P2[j].x, m.x);
                m.y = fmaf(cw2, P2[j].y, m.y);
                m.z = fmaf(cw2, P2[j].z, m.z);
                m.w = fmaf(cw2, P2[j].w, m.w);
                m.x = fmaf(-sw2, Q2[j].x, m.x);
                m.y = fmaf(-sw2, Q2[j].y, m.y);
                m.z = fmaf(-sw2, Q2[j].z, m.z);
                m.w = fmaf(-sw2, Q2[j].w, m.w);
                uint4 u;
                u.x = f2tf(m.x); u.y = f2tf(m.y);
                u.z = f2tf(m.z); u.w = f2tf(m.w);
                *(uint4*)(Ms + (pix * 64 + c) * 40 + oq * 4) = u;
            }
        }
        __syncthreads();

        // ---- GEMM: warp = pixel ----
        const int pix = wid;
        const int w = w0 + pix;
        float acc[16];
        #pragma unroll
        for (int i = 0; i < 16; i++) acc[i] = 0.f;

        #pragma unroll
        for (int kt = 0; kt < 8; kt++) {
            int ca = kt * 8 + tg;
            uint32_t a[4];
            const uint32_t* xb = Xt + (pix * 64 + ca) * 24;
            a[0] = xb[gid];
            a[1] = xb[gid + 8];
            a[2] = xb[4 * 24 + gid];
            a[3] = xb[4 * 24 + gid + 8];
            const uint32_t* mb = Ms + (pix * 64 + ca) * 40 + gid;
            #pragma unroll
            for (int nt = 0; nt < 4; nt++) {
                uint32_t b[2];
                b[0] = mb[nt * 8];
                b[1] = mb[4 * 40 + nt * 8];
                mma_tf32(acc + nt * 4, a, b);
            }
        }

        // ---- epilogue: store + stats ----
        size_t base0 = ((((size_t)gid * 128 + h) * 128) + w) * 128 + och * 32;
        #pragma unroll
        for (int nt = 0; nt < 4; nt++) {
            float d0 = acc[nt * 4 + 0], d1 = acc[nt * 4 + 1];
            float d2 = acc[nt * 4 + 2], d3 = acc[nt * 4 + 3];
            size_t o = base0 + nt * 8 + 2 * tg;
            *(float2*)(out + o) = make_float2(d0, d1);
            *(float2*)(out + 16777216 + o) = make_float2(d2, d3);
            ssum[0 * 8 + nt * 2 + 0] += d0;
            ssum[0 * 8 + nt * 2 + 1] += d1;
            ssum[1 * 8 + nt * 2 + 0] += d2;
            ssum[1 * 8 + nt * 2 + 1] += d3;
            ssq[0 * 8 + nt * 2 + 0] = fmaf(d0, d0, ssq[0 * 8 + nt * 2 + 0]);
            ssq[0 * 8 + nt * 2 + 1] = fmaf(d1, d1, ssq[0 * 8 + nt * 2 + 1]);
            ssq[1 * 8 + nt * 2 + 0] = fmaf(d2, d2, ssq[1 * 8 + nt * 2 + 0]);
            ssq[1 * 8 + nt * 2 + 1] = fmaf(d3, d3, ssq[1 * 8 + nt * 2 + 1]);
        }
    }

    // ---- BN stats: regs -> smem atomics -> global atomics ----
    __syncthreads();
    #pragma unroll
    for (int p = 0; p < 2; p++)
        #pragma unroll
        for (int nt = 0; nt < 4; nt++)
            #pragma unroll
            for (int d = 0; d < 2; d++) {
                int ol = nt * 8 + 2 * tg + d;
                atomicAdd(&red[(p * 32 + ol) * 2 + 0], ssum[p * 8 + nt * 2 + d]);
                atomicAdd(&red[(p * 32 + ol) * 2 + 1], ssq[p * 8 + nt * 2 + d]);
            }
    __syncthreads();
    if (t < 128) {
        int part2 = t >> 6, ol = (t >> 1) & 31, s = t & 1;
        atomicAdd(&g_stats[(part2 * 128 + och * 32 + ol) * 2 + s], red[t]);
    }
}

// ---------------------------------------------------------------------------
__global__ void bn_finalize_kernel(const float* __restrict__ gr,
                                   const float* __restrict__ br,
                                   const float* __restrict__ gi,
                                   const float* __restrict__ bi) {
    int t = threadIdx.x, part = t >> 7, o = t & 127;
    float sum = g_stats[t * 2 + 0], ss = g_stats[t * 2 + 1];
    const float inv = 1.f / 131072.f;
    float mean = sum * inv;
    float var = fmaf(-mean, mean, ss * inv);
    float gamma = part ? gi[o] : gr[o];
    float beta = part ? bi[o] : br[o];
    float a = gamma * rsqrtf(var + 1e-3f);
    g_bnp[t * 2 + 0] = a;
    g_bnp[t * 2 + 1] = fmaf(-mean, a, beta);
}

__global__ void bn_apply_kernel(float* __restrict__ out) {
    __shared__ float bp[512];
    int t = threadIdx.x;
    bp[t] = g_bnp[t];
    bp[t + 256] = g_bnp[t + 256];
    __syncthreads();
    const int total4 = 33554432 / 4;
    float4* o4 = (float4*)out;
    for (int i = blockIdx.x * blockDim.x + t; i < total4;
         i += gridDim.x * blockDim.x) {
        float4 x = o4[i];
        int e0 = i << 2;
        const float* b = bp + (e0 >> 24) * 256 + (e0 & 127) * 2;
        float v;
        v = fmaf(b[0], x.x, b[1]); x.x = v >= 0.f ? v : 0.2f * v;
        v = fmaf(b[2], x.y, b[3]); x.y = v >= 0.f ? v : 0.2f * v;
        v = fmaf(b[4], x.z, b[5]); x.z = v >= 0.f ? v : 0.2f * v;
        v = fmaf(b[6], x.w, b[7]); x.w = v >= 0.f ? v : 0.2f * v;
        o4[i] = x;
    }
}

// ---------------------------------------------------------------------------
extern "C" void kernel_launch(void* const* d_in, const int* in_sizes, int n_in,
                              void* d_out, int out_size) {
    const float* xr = (const float*)d_in[0];
    const float* xi = (const float*)d_in[1];
    const float* f  = (const float*)d_in[2];
    const float* gr = (const float*)d_in[3];
    const float* br = (const float*)d_in[4];
    const float* gi = (const float*)d_in[5];
    const float* bi = (const float*)d_in[6];
    float* out = (float*)d_out;

    cudaFuncSetAttribute(conv_mma_kernel,
                         cudaFuncAttributeMaxDynamicSharedMemorySize, SMEM_BYTES);

    zero_stats_kernel<<<1, 512>>>();
    precompute_pq_kernel<<<128, 256>>>(f);
    conv_mma_kernel<<<dim3(128, 4), 256, SMEM_BYTES>>>(xr, xi, out);
    bn_finalize_kernel<<<1, 256>>>(gr, br, gi, bi);
    bn_apply_kernel<<<2048, 256>>>(out);
}

// round 9
// speedup vs baseline: 1.0045x; 1.0045x over previous
#include <cuda_runtime.h>
#include <math.h>
#include <stdint.h>

#define TWO_PI 6.28318530717958647692f

// Scratch
__device__ float g_pq[128 * 3 * 2 * 64 * 128];   // [h][v][s(0=cos,1=sin)][c][o]
__device__ float g_stats[512];                   // [part][o][sum,sumsq]
__device__ float g_bnp[512];                     // [part][o][scale,shift]

__device__ __forceinline__ uint32_t f2tf(float x) {
    uint32_t u;
    asm("cvt.rna.tf32.f32 %0, %1;" : "=r"(u) : "f"(x));
    return u;
}
__device__ __forceinline__ void mma_tf32(float* d, const uint32_t* a,
                                         const uint32_t* b) {
    asm volatile(
        "mma.sync.aligned.m16n8k8.row.col.f32.tf32.tf32.f32 "
        "{%0,%1,%2,%3}, {%4,%5,%6,%7}, {%8,%9}, {%0,%1,%2,%3};"
        : "+f"(d[0]), "+f"(d[1]), "+f"(d[2]), "+f"(d[3])
        : "r"(a[0]), "r"(a[1]), "r"(a[2]), "r"(a[3]), "r"(b[0]), "r"(b[1]));
}

// ---------------------------------------------------------------------------
__global__ void zero_stats_kernel() {
    if (threadIdx.x < 512) g_stats[threadIdx.x] = 0.f;
}

// P_v[h][c][o] = sum_u cos(2*pi*h*u/128) * f[u][v][c][o]   (s=0)
// Q_v[h][c][o] = sum_u sin(...) * f[u][v][c][o]            (s=1)
__global__ void precompute_pq_kernel(const float* __restrict__ filters) {
    __shared__ float ct[128], st[128];
    int h = blockIdx.x, t = threadIdx.x;
    if (t < 128) {
        float s_, c_;
        sincosf(TWO_PI * (float)t * (1.f / 128.f), &s_, &c_);
        ct[t] = c_; st[t] = s_;
    }
    __syncthreads();
    for (int e = t; e < 3 * 2 * 64 * 128; e += blockDim.x) {
        int v = e >> 14, s = (e >> 13) & 1, co = e & 8191;
        float acc = 0.f;
        #pragma unroll
        for (int u = 0; u < 3; u++) {
            int a = (h * u) & 127;
            float tr = s ? st[a] : ct[a];
            acc = fmaf(tr, filters[(u * 3 + v) * 8192 + co], acc);
        }
        g_pq[((h * 3 + v) * 2 + s) * 8192 + co] = acc;
    }
}

// ---------------------------------------------------------------------------
// Conv kernel: grid (128 h, 4 och), 256 threads, tf32 mma.sync GEMM.
// Per 8-pixel group:
//  stage X: S=r+i rows 0..7, D=i-r rows 8..15, tf32 bits, Xt[(pix*64+c)*24 + r]
//  build M from register P/Q slices -> tf32 bits, Ms[(pix*64+c)*40 + o]
//  GEMM: warp = pixel, D[16x32] = Xrows[16x64] x M[64x32] via m16n8k8
#define XT_OFF 81920
#define CT_OFF 131072
#define ST_OFF 131584
#define RED_OFF 132096
#define SMEM_BYTES 132608

__global__ __launch_bounds__(256, 1) void conv_mma_kernel(
    const float* __restrict__ xr, const float* __restrict__ xi,
    float* __restrict__ out)
{
    extern __shared__ char smem[];
    uint32_t* Ms = (uint32_t*)smem;                   // [8*64][40]
    uint32_t* Xt = (uint32_t*)(smem + XT_OFF);        // [8*64][24]
    float* ct = (float*)(smem + CT_OFF);
    float* st = (float*)(smem + ST_OFF);
    float* red = (float*)(smem + RED_OFF);            // [2][32][2]

    const int h = blockIdx.x;
    const int och = blockIdx.y;
    const int t = threadIdx.x;
    const int lane = t & 31;
    const int wid = t >> 5;
    const int tg = lane & 3;       // threadID in group (k / col-pair)
    const int gid = lane >> 2;     // group id (row)

    if (t < 128) {
        float s_, c_;
        sincosf(TWO_PI * (float)t * (1.f / 128.f), &s_, &c_);
        ct[t] = c_; st[t] = s_;
        red[t] = 0.f;
    }

    // register-resident P/Q slice (verified R1 scheme): c = 2cp,2cp+1; 4 o's
    const int cp = t >> 3;
    const int oq = t & 7;
    const int obase = och * 32 + oq * 4;
    float4 P0[2], P1[2], Q1[2], P2[2], Q2[2];
    #pragma unroll
    for (int j = 0; j < 2; j++) {
        int c = 2 * cp + j;
        const float* b = g_pq + (size_t)h * 6 * 8192 + c * 128 + obase;
        P0[j] = *(const float4*)(b + 0 * 8192);
        P1[j] = *(const float4*)(b + 2 * 8192);
        Q1[j] = *(const float4*)(b + 3 * 8192);
        P2[j] = *(const float4*)(b + 4 * 8192);
        Q2[j] = *(const float4*)(b + 5 * 8192);
    }

    // BN stat accumulators: [part(2)][nt(4)][col-pair(2)]
    float ssum[16], ssq[16];
    #pragma unroll
    for (int i = 0; i < 16; i++) { ssum[i] = 0.f; ssq[i] = 0.f; }

    for (int w0 = 0; w0 < 128; w0 += 8) {
        __syncthreads();   // protect Ms/Xt vs previous group's GEMM reads

        // ---- stage X (tf32) ----
        #pragma unroll
        for (int k = 0; k < 4; k++) {
            int id = k * 256 + t;
            int pix = id >> 7;
            int n = id & 7;
            int c4 = ((id >> 3) & 15) << 2;
            size_t g = ((((size_t)n * 128 + h) * 128) + (w0 + pix)) * 64 + c4;
            float4 r = *(const float4*)(xr + g);
            float4 im = *(const float4*)(xi + g);
            uint32_t* xp = Xt + (pix * 64 + c4) * 24 + n;
            xp[0]       = f2tf(r.x + im.x);
            xp[24]      = f2tf(r.y + im.y);
            xp[48]      = f2tf(r.z + im.z);
            xp[72]      = f2tf(r.w + im.w);
            xp[8]       = f2tf(im.x - r.x);
            xp[32]      = f2tf(im.y - r.y);
            xp[56]      = f2tf(im.z - r.z);
            xp[80]      = f2tf(im.w - r.w);
        }

        // ---- build M (tf32) ----
        #pragma unroll
        for (int pix = 0; pix < 8; pix++) {
            int w = w0 + pix;
            float cw1 = ct[w], sw1 = st[w];
            int w2 = (w + w) & 127;
            float cw2 = ct[w2], sw2 = st[w2];
            #pragma unroll
            for (int j = 0; j < 2; j++) {
                int c = 2 * cp + j;
                float4 m;
                m.x = fmaf(cw1, P1[j].x, P0[j].x);
                m.y = fmaf(cw1, P1[j].y, P0[j].y);
                m.z = fmaf(cw1, P1[j].z, P0[j].z);
                m.w = fmaf(cw1, P1[j].w, P0[j].w);
                m.x = fmaf(-sw1, Q1[j].x, m.x);
                m.y = fmaf(-sw1, Q1[j].y, m.y);
                m.z = fmaf(-sw1, Q1[j].z, m.z);
                m.w = fmaf(-sw1, Q1[j].w, m.w);
                m.x = fmaf(cw2, P2[j].x, m.x);
                m.y = fmaf(cw2, P2[j].y, m.y);
                m.z = fmaf(cw2, P2[j].z, m.z);
                m.w = fmaf(cw2, P2[j].w, m.w);
                m.x = fmaf(-sw2, Q2[j].x, m.x);
                m.y = fmaf(-sw2, Q2[j].y, m.y);
                m.z = fmaf(-sw2, Q2[j].z, m.z);
                m.w = fmaf(-sw2, Q2[j].w, m.w);
                uint4 u;
                u.x = f2tf(m.x); u.y = f2tf(m.y);
                u.z = f2tf(m.z); u.w = f2tf(m.w);
                *(uint4*)(Ms + (pix * 64 + c) * 40 + oq * 4) = u;
            }
        }
        __syncthreads();

        // ---- GEMM: warp = pixel ----
        const int pix = wid;
        const int w = w0 + pix;
        float acc[16];
        #pragma unroll
        for (int i = 0; i < 16; i++) acc[i] = 0.f;

        #pragma unroll
        for (int kt = 0; kt < 8; kt++) {
            int ca = kt * 8 + tg;
            uint32_t a[4];
            const uint32_t* xb = Xt + (pix * 64 + ca) * 24;
            a[0] = xb[gid];
            a[1] = xb[gid + 8];
            a[2] = xb[4 * 24 + gid];
            a[3] = xb[4 * 24 + gid + 8];
            const uint32_t* mb = Ms + (pix * 64 + ca) * 40 + gid;
            #pragma unroll
            for (int nt = 0; nt < 4; nt++) {
                uint32_t b[2];
                b[0] = mb[nt * 8];
                b[1] = mb[4 * 40 + nt * 8];
                mma_tf32(acc + nt * 4, a, b);
            }
        }

        // ---- epilogue: store + stats ----
        size_t base0 = ((((size_t)gid * 128 + h) * 128) + w) * 128 + och * 32;
        #pragma unroll
        for (int nt = 0; nt < 4; nt++) {
            float d0 = acc[nt * 4 + 0], d1 = acc[nt * 4 + 1];
            float d2 = acc[nt * 4 + 2], d3 = acc[nt * 4 + 3];
            size_t o = base0 + nt * 8 + 2 * tg;
            *(float2*)(out + o) = make_float2(d0, d1);
            *(float2*)(out + 16777216 + o) = make_float2(d2, d3);
            ssum[0 * 8 + nt * 2 + 0] += d0;
            ssum[0 * 8 + nt * 2 + 1] += d1;
            ssum[1 * 8 + nt * 2 + 0] += d2;
            ssum[1 * 8 + nt * 2 + 1] += d3;
            ssq[0 * 8 + nt * 2 + 0] = fmaf(d0, d0, ssq[0 * 8 + nt * 2 + 0]);
            ssq[0 * 8 + nt * 2 + 1] = fmaf(d1, d1, ssq[0 * 8 + nt * 2 + 1]);
            ssq[1 * 8 + nt * 2 + 0] = fmaf(d2, d2, ssq[1 * 8 + nt * 2 + 0]);
            ssq[1 * 8 + nt * 2 + 1] = fmaf(d3, d3, ssq[1 * 8 + nt * 2 + 1]);
        }
    }

    // ---- BN stats: regs -> smem atomics -> global atomics ----
    __syncthreads();
    #pragma unroll
    for (int p = 0; p < 2; p++)
        #pragma unroll
        for (int nt = 0; nt < 4; nt++)
            #pragma unroll
            for (int d = 0; d < 2; d++) {
                int ol = nt * 8 + 2 * tg + d;
                atomicAdd(&red[(p * 32 + ol) * 2 + 0], ssum[p * 8 + nt * 2 + d]);
                atomicAdd(&red[(p * 32 + ol) * 2 + 1], ssq[p * 8 + nt * 2 + d]);
            }
    __syncthreads();
    if (t < 128) {
        int part2 = t >> 6, ol = (t >> 1) & 31, s = t & 1;
        atomicAdd(&g_stats[(part2 * 128 + och * 32 + ol) * 2 + s], red[t]);
    }
}

// ---------------------------------------------------------------------------
__global__ void bn_finalize_kernel(const float* __restrict__ gr,
                                   const float* __restrict__ br,
                                   const float* __restrict__ gi,
                                   const float* __restrict__ bi) {
    int t = threadIdx.x, part = t >> 7, o = t & 127;
    float sum = g_stats[t * 2 + 0], ss = g_stats[t * 2 + 1];
    const float inv = 1.f / 131072.f;
    float mean = sum * inv;
    float var = fmaf(-mean, mean, ss * inv);
    float gamma = part ? gi[o] : gr[o];
    float beta = part ? bi[o] : br[o];
    float a = gamma * rsqrtf(var + 1e-3f);
    g_bnp[t * 2 + 0] = a;
    g_bnp[t * 2 + 1] = fmaf(-mean, a, beta);
}

__global__ void bn_apply_kernel(float* __restrict__ out) {
    __shared__ float bp[512];
    int t = threadIdx.x;
    bp[t] = g_bnp[t];
    bp[t + 256] = g_bnp[t + 256];
    __syncthreads();
    const int total4 = 33554432 / 4;
    float4* o4 = (float4*)out;
    for (int i = blockIdx.x * blockDim.x + t; i < total4;
         i += gridDim.x * blockDim.x) {
        float4 x = o4[i];
        int e0 = i << 2;
        const float* b = bp + (e0 >> 24) * 256 + (e0 & 127) * 2;
        float v;
        v = fmaf(b[0], x.x, b[1]); x.x = v >= 0.f ? v : 0.2f * v;
        v = fmaf(b[2], x.y, b[3]); x.y = v >= 0.f ? v : 0.2f * v;
        v = fmaf(b[4], x.z, b[5]); x.z = v >= 0.f ? v : 0.2f * v;
        v = fmaf(b[6], x.w, b[7]); x.w = v >= 0.f ? v : 0.2f * v;
        o4[i] = x;
    }
}

// ---------------------------------------------------------------------------
extern "C" void kernel_launch(void* const* d_in, const int* in_sizes, int n_in,
                              void* d_out, int out_size) {
    const float* xr = (const float*)d_in[0];
    const float* xi = (const float*)d_in[1];
    const float* f  = (const float*)d_in[2];
    const float* gr = (const float*)d_in[3];
    const float* br = (const float*)d_in[4];
    const float* gi = (const float*)d_in[5];
    const float* bi = (const float*)d_in[6];
    float* out = (float*)d_out;

    cudaFuncSetAttribute(conv_mma_kernel,
                         cudaFuncAttributeMaxDynamicSharedMemorySize, SMEM_BYTES);

    zero_stats_kernel<<<1, 512>>>();
    precompute_pq_kernel<<<128, 256>>>(f);
    conv_mma_kernel<<<dim3(128, 4), 256, SMEM_BYTES>>>(xr, xi, out);
    bn_finalize_kernel<<<1, 256>>>(gr, br, gi, bi);
    bn_apply_kernel<<<2048, 256>>>(out);
}

// round 10
// speedup vs baseline: 1.7525x; 1.7446x over previous
#include <cuda_runtime.h>
#include <math.h>
#include <stdint.h>

#define TWO_PI 6.28318530717958647692f

// Scratch
__device__ float g_Bf[128 * 40960];   // [h][j(5)][kt(8)][o(128)][tg(4)][slot(2)] = 21MB
__device__ float g_stats[512];        // [(part*128+o)*2 + {sum,sq}]
__device__ float g_bnp[512];          // [(part*128+o)*2 + {scale,shift}]

__device__ __forceinline__ uint32_t f2tf(float x) {
    uint32_t u;
    asm("cvt.rna.tf32.f32 %0, %1;" : "=r"(u) : "f"(x));
    return u;
}
__device__ __forceinline__ void mma_tf32(float* d, const uint32_t* a,
                                         const uint32_t* b) {
    asm volatile(
        "mma.sync.aligned.m16n8k8.row.col.f32.tf32.tf32.f32 "
        "{%0,%1,%2,%3}, {%4,%5,%6,%7}, {%8,%9}, {%0,%1,%2,%3};"
        : "+f"(d[0]), "+f"(d[1]), "+f"(d[2]), "+f"(d[3])
        : "r"(a[0]), "r"(a[1]), "r"(a[2]), "r"(a[3]), "r"(b[0]), "r"(b[1]));
}

// ---------------------------------------------------------------------------
__global__ void zero_stats_kernel() {
    if (threadIdx.x < 512) g_stats[threadIdx.x] = 0.f;
}

// B_j[o][c], j in {P0, P1, -Q1, P2, -Q2}, stored fragment-friendly:
// g_Bf[h][j][kt][o][tg][slot] = B_j[o][c = kt*8 + tg + slot*4]
__global__ void precompute_B_kernel(const float* __restrict__ filters) {
    __shared__ float ct[128], st[128];
    int h = blockIdx.x, t = threadIdx.x;
    if (t < 128) {
        float s_, c_;
        sincosf(TWO_PI * (float)t * (1.f / 128.f), &s_, &c_);
        ct[t] = c_; st[t] = s_;
    }
    __syncthreads();
    for (int e = t; e < 40960; e += blockDim.x) {
        int slot = e & 1;
        int tg = (e >> 1) & 3;
        int o = (e >> 3) & 127;
        int kt = (e >> 10) & 7;
        int j = e >> 13;
        int c = kt * 8 + tg + slot * 4;
        int v = (j + 1) >> 1;                       // {0,1,1,2,2}
        bool sn = (j > 0) && ((j & 1) == 0);        // j==2 || j==4 -> -Q
        float acc = 0.f;
        #pragma unroll
        for (int u = 0; u < 3; u++) {
            int a = (h * u) & 127;
            float tr = sn ? st[a] : ct[a];
            acc = fmaf(tr, filters[(u * 3 + v) * 8192 + c * 128 + o], acc);
        }
        g_Bf[h * 40960 + e] = sn ? -acc : acc;
    }
}

// ---------------------------------------------------------------------------
// Conv: 128 CTAs (one per h), 256 threads (8 warps), no main-loop barriers.
// Warp = one w per iteration (16 iterations). m-tile rows: gid -> (n=gid>>1,
// part=gid&1); rows gid+8 -> n+4 same part. K=320 = 5 coef-scaled j-chunks
// of 64 channels against smem-resident B_j. Accumulators stay in registers.
#define SMEM_CONV (163840 + 2048)

__global__ __launch_bounds__(256, 1) void conv_mma_kernel(
    const float* __restrict__ xr, const float* __restrict__ xi,
    float* __restrict__ out)
{
    extern __shared__ float smem[];
    float2* Bs = (float2*)smem;          // 20480 float2 = 160KB
    float* red = smem + 40960;           // 512 floats

    const int h = blockIdx.x, t = threadIdx.x;
    const int lane = t & 31, wid = t >> 5;
    const int gid = lane >> 2, tg = lane & 3;
    const int n0 = gid >> 1, part = gid & 1;

    // load resident B (coalesced float4)
    {
        const float4* src = (const float4*)(g_Bf + h * 40960);
        float4* dst = (float4*)Bs;
        for (int g = t; g < 10240; g += 256) dst[g] = src[g];
    }
    for (int i = t; i < 512; i += 256) red[i] = 0.f;
    __syncthreads();

    // persistent BN stat registers: per nt, o-pair (2tg, 2tg+1)
    float ss0[16], qq0[16], ss1[16], qq1[16];
    #pragma unroll
    for (int i = 0; i < 16; i++) { ss0[i] = 0.f; qq0[i] = 0.f; ss1[i] = 0.f; qq1[i] = 0.f; }

    const float* xr0 = xr + ((size_t)(n0 * 128 + h) * 128) * 64;
    const float* xi0 = xi + ((size_t)(n0 * 128 + h) * 128) * 64;
    const float* xr4 = xr + ((size_t)((n0 + 4) * 128 + h) * 128) * 64;
    const float* xi4 = xi + ((size_t)((n0 + 4) * 128 + h) * 128) * 64;

    for (int it = 0; it < 16; it++) {
        const int w = it * 8 + wid;
        const float* pr0 = xr0 + w * 64;
        const float* pi0 = xi0 + w * 64;
        const float* pr4 = xr4 + w * 64;
        const float* pi4 = xi4 + w * 64;

        // raw A fragments (S or D by part), all 8 k-tiles
        float rawA[32];
        #pragma unroll
        for (int kt = 0; kt < 8; kt++) {
            int c0 = kt * 8 + tg, c1 = c0 + 4;
            float r0 = pr0[c0], i0 = pi0[c0];
            float r4 = pr4[c0], i4 = pi4[c0];
            float r0b = pr0[c1], i0b = pi0[c1];
            float r4b = pr4[c1], i4b = pi4[c1];
            rawA[kt * 4 + 0] = part ? (i0 - r0) : (r0 + i0);
            rawA[kt * 4 + 1] = part ? (i4 - r4) : (r4 + i4);
            rawA[kt * 4 + 2] = part ? (i0b - r0b) : (r0b + i0b);
            rawA[kt * 4 + 3] = part ? (i4b - r4b) : (r4b + i4b);
        }

        float s1, c1f, s2, c2f;
        sincosf(TWO_PI * (float)w * (1.f / 128.f), &s1, &c1f);
        sincosf(TWO_PI * (float)((2 * w) & 127) * (1.f / 128.f), &s2, &c2f);
        const float coef[5] = {1.f, c1f, s1, c2f, s2};

        float acc[16][4];
        #pragma unroll
        for (int nt = 0; nt < 16; nt++) {
            acc[nt][0] = 0.f; acc[nt][1] = 0.f; acc[nt][2] = 0.f; acc[nt][3] = 0.f;
        }

        #pragma unroll
        for (int j = 0; j < 5; j++) {
            const float cf = coef[j];
            #pragma unroll
            for (int kt = 0; kt < 8; kt++) {
                uint32_t a[4];
                a[0] = f2tf(cf * rawA[kt * 4 + 0]);
                a[1] = f2tf(cf * rawA[kt * 4 + 1]);
                a[2] = f2tf(cf * rawA[kt * 4 + 2]);
                a[3] = f2tf(cf * rawA[kt * 4 + 3]);
                // one conflict-free lds.64 per (nt): {B[k=tg][o], B[k=tg+4][o]}
                const float2* bp = Bs + ((j * 8 + kt) * 128 + gid) * 4 + tg;
                #pragma unroll
                for (int nt = 0; nt < 16; nt++) {
                    float2 b = bp[nt * 32];
                    mma_tf32(acc[nt], a, (const uint32_t*)&b);
                }
            }
        }

        // epilogue: store raw conv outputs + accumulate BN stats
        size_t ob = (size_t)part * 16777216 +
                    (((size_t)(n0 * 128 + h)) * 128 + w) * 128;
        size_t ob4 = ob + (size_t)4 * 128 * 128 * 128;
        #pragma unroll
        for (int nt = 0; nt < 16; nt++) {
            int o = nt * 8 + 2 * tg;
            *(float2*)(out + ob + o)  = make_float2(acc[nt][0], acc[nt][1]);
            *(float2*)(out + ob4 + o) = make_float2(acc[nt][2], acc[nt][3]);
            ss0[nt] += acc[nt][0] + acc[nt][2];
            qq0[nt] = fmaf(acc[nt][0], acc[nt][0], qq0[nt]);
            qq0[nt] = fmaf(acc[nt][2], acc[nt][2], qq0[nt]);
            ss1[nt] += acc[nt][1] + acc[nt][3];
            qq1[nt] = fmaf(acc[nt][1], acc[nt][1], qq1[nt]);
            qq1[nt] = fmaf(acc[nt][3], acc[nt][3], qq1[nt]);
        }
    }

    // stats: shuffle-reduce over same-part lanes (lane^8, lane^16), then smem
    #pragma unroll
    for (int nt = 0; nt < 16; nt++) {
        ss0[nt] += __shfl_xor_sync(~0u, ss0[nt], 8);
        ss0[nt] += __shfl_xor_sync(~0u, ss0[nt], 16);
        qq0[nt] += __shfl_xor_sync(~0u, qq0[nt], 8);
        qq0[nt] += __shfl_xor_sync(~0u, qq0[nt], 16);
        ss1[nt] += __shfl_xor_sync(~0u, ss1[nt], 8);
        ss1[nt] += __shfl_xor_sync(~0u, ss1[nt], 16);
        qq1[nt] += __shfl_xor_sync(~0u, qq1[nt], 8);
        qq1[nt] += __shfl_xor_sync(~0u, qq1[nt], 16);
    }
    if (lane < 8) {   // gid in {0,1}: part = gid, tg = lane&3
        #pragma unroll
        for (int nt = 0; nt < 16; nt++) {
            int o = nt * 8 + 2 * tg;
            atomicAdd(&red[(part * 128 + o) * 2 + 0], ss0[nt]);
            atomicAdd(&red[(part * 128 + o) * 2 + 1], qq0[nt]);
            atomicAdd(&red[(part * 128 + o + 1) * 2 + 0], ss1[nt]);
            atomicAdd(&red[(part * 128 + o + 1) * 2 + 1], qq1[nt]);
        }
    }
    __syncthreads();
    for (int i = t; i < 512; i += 256) atomicAdd(&g_stats[i], red[i]);
}

// ---------------------------------------------------------------------------
__global__ void bn_finalize_kernel(const float* __restrict__ gr,
                                   const float* __restrict__ br,
                                   const float* __restrict__ gi,
                                   const float* __restrict__ bi) {
    int t = threadIdx.x, part = t >> 7, o = t & 127;
    float sum = g_stats[t * 2 + 0], ss = g_stats[t * 2 + 1];
    const float inv = 1.f / 131072.f;
    float mean = sum * inv;
    float var = fmaf(-mean, mean, ss * inv);
    float gamma = part ? gi[o] : gr[o];
    float beta = part ? bi[o] : br[o];
    float a = gamma * rsqrtf(var + 1e-3f);
    g_bnp[t * 2 + 0] = a;
    g_bnp[t * 2 + 1] = fmaf(-mean, a, beta);
}

__global__ void bn_apply_kernel(float* __restrict__ out) {
    __shared__ float bp[512];
    int t = threadIdx.x;
    bp[t] = g_bnp[t];
    bp[t + 256] = g_bnp[t + 256];
    __syncthreads();
    const int total4 = 33554432 / 4;
    float4* o4 = (float4*)out;
    for (int i = blockIdx.x * blockDim.x + t; i < total4;
         i += gridDim.x * blockDim.x) {
        float4 x = o4[i];
        int e0 = i << 2;
        const float* b = bp + (e0 >> 24) * 256 + (e0 & 127) * 2;
        float v;
        v = fmaf(b[0], x.x, b[1]); x.x = v >= 0.f ? v : 0.2f * v;
        v = fmaf(b[2], x.y, b[3]); x.y = v >= 0.f ? v : 0.2f * v;
        v = fmaf(b[4], x.z, b[5]); x.z = v >= 0.f ? v : 0.2f * v;
        v = fmaf(b[6], x.w, b[7]); x.w = v >= 0.f ? v : 0.2f * v;
        o4[i] = x;
    }
}

// ---------------------------------------------------------------------------
extern "C" void kernel_launch(void* const* d_in, const int* in_sizes, int n_in,
                              void* d_out, int out_size) {
    const float* xr = (const float*)d_in[0];
    const float* xi = (const float*)d_in[1];
    const float* f  = (const float*)d_in[2];
    const float* gr = (const float*)d_in[3];
    const float* br = (const float*)d_in[4];
    const float* gi = (const float*)d_in[5];
    const float* bi = (const float*)d_in[6];
    float* out = (float*)d_out;

    cudaFuncSetAttribute(conv_mma_kernel,
                         cudaFuncAttributeMaxDynamicSharedMemorySize, SMEM_CONV);

    zero_stats_kernel<<<1, 512>>>();
    precompute_B_kernel<<<128, 256>>>(f);
    conv_mma_kernel<<<128, 256, SMEM_CONV>>>(xr, xi, out);
    bn_finalize_kernel<<<1, 256>>>(gr, br, gi, bi);
    bn_apply_kernel<<<2048, 256>>>(out);
}